// round 2
// baseline (speedup 1.0000x reference)
#include <cuda_runtime.h>

#define BB 4
#define NN 4096
#define FF 128
#define LALPHA 0.2f

// Scratch (no allocations allowed)
__device__ float g_Wh[BB * NN * FF];   // 8 MB
__device__ float g_si[BB * NN];
__device__ float g_sj[BB * NN];

// ---------- f32x2 packed helpers (Blackwell FFMA2 via PTX) ----------
__device__ __forceinline__ unsigned long long pack2(float lo, float hi) {
    unsigned long long r;
    asm("mov.b64 %0, {%1, %2};" : "=l"(r) : "f"(lo), "f"(hi));
    return r;
}
__device__ __forceinline__ unsigned long long bcast2(float v) {
    unsigned long long r;
    asm("mov.b64 %0, {%1, %1};" : "=l"(r) : "f"(v));
    return r;
}
__device__ __forceinline__ void fma2(unsigned long long& d,
                                     unsigned long long a,
                                     unsigned long long b) {
    asm("fma.rn.f32x2 %0, %1, %2, %0;" : "+l"(d) : "l"(a), "l"(b));
}
__device__ __forceinline__ float2 unpack2(unsigned long long v) {
    float2 f;
    asm("mov.b64 {%0, %1}, %2;" : "=f"(f.x), "=f"(f.y) : "l"(v));
    return f;
}

// =====================================================================
// Kernel A: Wh = h @ W   (per CTA: 64 rows x 128 cols, K=128 in chunks of 32)
// =====================================================================
__global__ void __launch_bounds__(128) k_wh(const float* __restrict__ h,
                                            const float* __restrict__ W) {
    const int b = blockIdx.y;
    const int i0 = blockIdx.x * 64;

    __shared__ float hsT[32][68];   // [k][r], padded for float4-aligned reads
    __shared__ float Ws[32][128];   // [k][f]

    const int tid = threadIdx.x;
    const int fgrp = tid & 15, rgrp = tid >> 4;
    const int rbase = rgrp * 8, fbase = fgrp * 8;

    unsigned long long acc[8][4];
#pragma unroll
    for (int r = 0; r < 8; r++)
#pragma unroll
        for (int c = 0; c < 4; c++) acc[r][c] = 0ULL;  // {0.f,0.f}

    for (int k0 = 0; k0 < FF; k0 += 32) {
        __syncthreads();
        // load h tile transposed: rows i0..i0+63, k0..k0+31
        for (int idx = tid; idx < 64 * 8; idx += 128) {
            int r = idx >> 3, kq = idx & 7;
            float4 v = *(const float4*)(h + ((size_t)(b * NN + i0 + r)) * FF + k0 + kq * 4);
            hsT[kq * 4 + 0][r] = v.x;
            hsT[kq * 4 + 1][r] = v.y;
            hsT[kq * 4 + 2][r] = v.z;
            hsT[kq * 4 + 3][r] = v.w;
        }
        // load W chunk
        for (int idx = tid; idx < 32 * 32; idx += 128) {
            int kk = idx >> 5, fq = idx & 31;
            *(float4*)&Ws[kk][fq * 4] = *(const float4*)(W + (size_t)(k0 + kk) * FF + fq * 4);
        }
        __syncthreads();

#pragma unroll 4
        for (int kk = 0; kk < 32; kk++) {
            float4 w0 = *(float4*)&hsT[kk][rbase];
            float4 w1 = *(float4*)&hsT[kk][rbase + 4];
            float4 h0 = *(float4*)&Ws[kk][fbase];
            float4 h1 = *(float4*)&Ws[kk][fbase + 4];
            unsigned long long hh[4];
            hh[0] = pack2(h0.x, h0.y); hh[1] = pack2(h0.z, h0.w);
            hh[2] = pack2(h1.x, h1.y); hh[3] = pack2(h1.z, h1.w);
            float wr[8] = {w0.x, w0.y, w0.z, w0.w, w1.x, w1.y, w1.z, w1.w};
#pragma unroll
            for (int r = 0; r < 8; r++) {
                unsigned long long wb = bcast2(wr[r]);
#pragma unroll
                for (int c = 0; c < 4; c++) fma2(acc[r][c], wb, hh[c]);
            }
        }
    }

#pragma unroll
    for (int r = 0; r < 8; r++) {
        float2 a0 = unpack2(acc[r][0]);
        float2 a1 = unpack2(acc[r][1]);
        float2 a2 = unpack2(acc[r][2]);
        float2 a3 = unpack2(acc[r][3]);
        size_t row = (size_t)(b * NN) + i0 + rbase + r;
        float4 o0 = make_float4(a0.x, a0.y, a1.x, a1.y);
        float4 o1 = make_float4(a2.x, a2.y, a3.x, a3.y);
        *(float4*)(g_Wh + row * FF + fbase) = o0;
        *(float4*)(g_Wh + row * FF + fbase + 4) = o1;
    }
}

// =====================================================================
// Kernel B: si = Wh . a[:128], sj = Wh . a[128:]   (one warp per row-group)
// =====================================================================
__global__ void k_sisj(const float* __restrict__ a) {
    const int lane = threadIdx.x & 31;
    const int warp = (blockIdx.x * blockDim.x + threadIdx.x) >> 5;
    const int nwarps = (gridDim.x * blockDim.x) >> 5;

    float4 ai = *(const float4*)(a + lane * 4);
    float4 aj = *(const float4*)(a + FF + lane * 4);

    for (int row = warp; row < BB * NN; row += nwarps) {
        float4 wh = *(const float4*)(g_Wh + (size_t)row * FF + lane * 4);
        float si = wh.x * ai.x + wh.y * ai.y + wh.z * ai.z + wh.w * ai.w;
        float sj = wh.x * aj.x + wh.y * aj.y + wh.z * aj.z + wh.w * aj.w;
#pragma unroll
        for (int o = 16; o; o >>= 1) {
            si += __shfl_xor_sync(0xFFFFFFFFu, si, o);
            sj += __shfl_xor_sync(0xFFFFFFFFu, sj, o);
        }
        if (lane == 0) {
            g_si[row] = si;
            g_sj[row] = sj;
        }
    }
}

// =====================================================================
// Kernel C: fused masked-softmax + P @ Wh + ELU.
// Per CTA: 64 rows (i), full 128 features; streams j in tiles of 32.
// Single pass (no max subtraction needed: |e| is small, exp fits fp32).
// =====================================================================
__global__ void __launch_bounds__(128) k_attn(const int* __restrict__ adj,
                                              float* __restrict__ out) {
    const int b = blockIdx.y;
    const int i0 = blockIdx.x * 64;

    __shared__ float Whs[32][128];   // Wh j-tile    (16 KB)
    __shared__ float wsm[32][68];    // weights [jj][row], padded (8.5 KB)
    __shared__ float sjs[32];
    __shared__ float zbuf[64][2];
    __shared__ float zfin[64];

    const int tid = threadIdx.x;

    // w-generation role: thread -> (row, half of j-tile)
    const int wr = tid >> 1;
    const int whalf = tid & 1;
    const float si_r = g_si[b * NN + i0 + wr];
    float zloc = 0.f;
    const int* adjRow = adj + ((size_t)(b * NN + i0 + wr)) * NN;

    // compute role: thread -> (8 rows, 8 features)
    const int fgrp = tid & 15, rgrp = tid >> 4;
    const int rbase = rgrp * 8, fbase = fgrp * 8;

    unsigned long long acc[8][4];
#pragma unroll
    for (int r = 0; r < 8; r++)
#pragma unroll
        for (int c = 0; c < 4; c++) acc[r][c] = 0ULL;

    const float* WhB = g_Wh + (size_t)b * NN * FF;

    for (int j0 = 0; j0 < NN; j0 += 32) {
        __syncthreads();  // previous tile fully consumed

        // stage Wh j-tile (32 x 128 = 1024 float4, coalesced, L2-resident)
        for (int idx = tid; idx < 1024; idx += 128) {
            int jj = idx >> 5, fq = idx & 31;
            *(float4*)&Whs[jj][fq * 4] =
                *(const float4*)(WhB + (size_t)(j0 + jj) * FF + fq * 4);
        }
        if (tid < 32) sjs[tid] = g_sj[b * NN + j0 + tid];
        __syncthreads();

        // generate weights: w = adj ? exp(lrelu(si+sj)) : 0
        {
            const int4* ap = (const int4*)(adjRow + j0 + whalf * 16);
#pragma unroll
            for (int q = 0; q < 4; q++) {
                int4 av = ap[q];
                int jj = whalf * 16 + q * 4;
                float e0 = si_r + sjs[jj + 0]; e0 = e0 > 0.f ? e0 : LALPHA * e0;
                float e1 = si_r + sjs[jj + 1]; e1 = e1 > 0.f ? e1 : LALPHA * e1;
                float e2 = si_r + sjs[jj + 2]; e2 = e2 > 0.f ? e2 : LALPHA * e2;
                float e3 = si_r + sjs[jj + 3]; e3 = e3 > 0.f ? e3 : LALPHA * e3;
                float v0 = av.x > 0 ? __expf(e0) : 0.f;
                float v1 = av.y > 0 ? __expf(e1) : 0.f;
                float v2 = av.z > 0 ? __expf(e2) : 0.f;
                float v3 = av.w > 0 ? __expf(e3) : 0.f;
                wsm[jj + 0][wr] = v0;
                wsm[jj + 1][wr] = v1;
                wsm[jj + 2][wr] = v2;
                wsm[jj + 3][wr] = v3;
                zloc += (v0 + v1) + (v2 + v3);
            }
        }
        __syncthreads();

        // accumulate: acc[r][f] += w[jj][r] * Wh[jj][f]
#pragma unroll 2
        for (int jj = 0; jj < 32; jj++) {
            float4 w0 = *(float4*)&wsm[jj][rbase];
            float4 w1 = *(float4*)&wsm[jj][rbase + 4];
            float4 h0 = *(float4*)&Whs[jj][fbase];
            float4 h1 = *(float4*)&Whs[jj][fbase + 4];
            unsigned long long hh[4];
            hh[0] = pack2(h0.x, h0.y); hh[1] = pack2(h0.z, h0.w);
            hh[2] = pack2(h1.x, h1.y); hh[3] = pack2(h1.z, h1.w);
            float wv[8] = {w0.x, w0.y, w0.z, w0.w, w1.x, w1.y, w1.z, w1.w};
#pragma unroll
            for (int r = 0; r < 8; r++) {
                unsigned long long wb = bcast2(wv[r]);
#pragma unroll
                for (int c = 0; c < 4; c++) fma2(acc[r][c], wb, hh[c]);
            }
        }
    }

    // reduce Z per row
    zbuf[wr][whalf] = zloc;
    __syncthreads();
    if (tid < 64) zfin[tid] = zbuf[tid][0] + zbuf[tid][1];
    __syncthreads();

    // epilogue: normalize + ELU, coalesced float4 stores
#pragma unroll
    for (int r = 0; r < 8; r++) {
        float zi = 1.0f / zfin[rbase + r];
        float2 a0 = unpack2(acc[r][0]);
        float2 a1 = unpack2(acc[r][1]);
        float2 a2 = unpack2(acc[r][2]);
        float2 a3 = unpack2(acc[r][3]);
        float v[8] = {a0.x, a0.y, a1.x, a1.y, a2.x, a2.y, a3.x, a3.y};
#pragma unroll
        for (int k = 0; k < 8; k++) {
            float x = v[k] * zi;
            v[k] = x > 0.f ? x : (__expf(x) - 1.0f);
        }
        size_t row = (size_t)(b * NN) + i0 + rbase + r;
        *(float4*)(out + row * FF + fbase) = make_float4(v[0], v[1], v[2], v[3]);
        *(float4*)(out + row * FF + fbase + 4) = make_float4(v[4], v[5], v[6], v[7]);
    }
}

// =====================================================================
extern "C" void kernel_launch(void* const* d_in, const int* in_sizes, int n_in,
                              void* d_out, int out_size) {
    const float* h   = (const float*)d_in[0];
    const int*   adj = (const int*)d_in[1];
    const float* W   = (const float*)d_in[2];
    const float* a   = (const float*)d_in[3];
    float* out = (float*)d_out;

    k_wh<<<dim3(NN / 64, BB), 128>>>(h, W);
    k_sisj<<<128, 256>>>(a);
    k_attn<<<dim3(NN / 64, BB), 128>>>(adj, out);
}

// round 3
// speedup vs baseline: 1.2622x; 1.2622x over previous
#include <cuda_runtime.h>

#define BB 4
#define NN 4096
#define FF 128
#define LALPHA 0.2f
#define TJ 16

// Scratch (no allocations allowed)
__device__ float g_WhTh[BB * FF * NN];   // Wh^T hi (tf32), [b][f][i]  8MB
__device__ float g_WhTl[BB * FF * NN];   // Wh^T lo (tf32)             8MB
__device__ float g_si[BB * NN];
__device__ float g_sj[BB * NN];

// ---------- f32x2 packed helpers (for k_wh) ----------
__device__ __forceinline__ unsigned long long pack2(float lo, float hi) {
    unsigned long long r;
    asm("mov.b64 %0, {%1, %2};" : "=l"(r) : "f"(lo), "f"(hi));
    return r;
}
__device__ __forceinline__ unsigned long long bcast2(float v) {
    unsigned long long r;
    asm("mov.b64 %0, {%1, %1};" : "=l"(r) : "f"(v));
    return r;
}
__device__ __forceinline__ void fma2(unsigned long long& d,
                                     unsigned long long a,
                                     unsigned long long b) {
    asm("fma.rn.f32x2 %0, %1, %2, %0;" : "+l"(d) : "l"(a), "l"(b));
}
__device__ __forceinline__ float2 unpack2(unsigned long long v) {
    float2 f;
    asm("mov.b64 {%0, %1}, %2;" : "=f"(f.x), "=f"(f.y) : "l"(v));
    return f;
}

// ---------- tf32 helpers ----------
__device__ __forceinline__ unsigned f2tf32(float x) {
    unsigned r;
    asm("cvt.rn.tf32.f32 %0, %1;" : "=r"(r) : "f"(x));
    return r;
}
__device__ __forceinline__ void mma_tf32(float* c, const unsigned* a,
                                         unsigned b0, unsigned b1) {
    asm volatile(
        "mma.sync.aligned.m16n8k8.row.col.f32.tf32.tf32.f32 "
        "{%0,%1,%2,%3}, {%4,%5,%6,%7}, {%8,%9}, {%0,%1,%2,%3};"
        : "+f"(c[0]), "+f"(c[1]), "+f"(c[2]), "+f"(c[3])
        : "r"(a[0]), "r"(a[1]), "r"(a[2]), "r"(a[3]), "r"(b0), "r"(b1));
}

// =====================================================================
// Kernel A: Wh = h @ W ; epilogue splits into tf32 hi/lo and stores
// transposed as WhT[b][f][i].
// =====================================================================
__global__ void __launch_bounds__(128) k_wh(const float* __restrict__ h,
                                            const float* __restrict__ W) {
    const int b = blockIdx.y;
    const int i0 = blockIdx.x * 64;

    __shared__ float hsT[32][68];
    __shared__ float Ws[32][128];

    const int tid = threadIdx.x;
    const int fgrp = tid & 15, rgrp = tid >> 4;
    const int rbase = rgrp * 8, fbase = fgrp * 8;

    unsigned long long acc[8][4];
#pragma unroll
    for (int r = 0; r < 8; r++)
#pragma unroll
        for (int c = 0; c < 4; c++) acc[r][c] = 0ULL;

    for (int k0 = 0; k0 < FF; k0 += 32) {
        __syncthreads();
        for (int idx = tid; idx < 64 * 8; idx += 128) {
            int r = idx >> 3, kq = idx & 7;
            float4 v = *(const float4*)(h + ((size_t)(b * NN + i0 + r)) * FF + k0 + kq * 4);
            hsT[kq * 4 + 0][r] = v.x;
            hsT[kq * 4 + 1][r] = v.y;
            hsT[kq * 4 + 2][r] = v.z;
            hsT[kq * 4 + 3][r] = v.w;
        }
        for (int idx = tid; idx < 32 * 32; idx += 128) {
            int kk = idx >> 5, fq = idx & 31;
            *(float4*)&Ws[kk][fq * 4] = *(const float4*)(W + (size_t)(k0 + kk) * FF + fq * 4);
        }
        __syncthreads();

#pragma unroll 4
        for (int kk = 0; kk < 32; kk++) {
            float4 w0 = *(float4*)&hsT[kk][rbase];
            float4 w1 = *(float4*)&hsT[kk][rbase + 4];
            float4 h0 = *(float4*)&Ws[kk][fbase];
            float4 h1 = *(float4*)&Ws[kk][fbase + 4];
            unsigned long long hh[4];
            hh[0] = pack2(h0.x, h0.y); hh[1] = pack2(h0.z, h0.w);
            hh[2] = pack2(h1.x, h1.y); hh[3] = pack2(h1.z, h1.w);
            float wr[8] = {w0.x, w0.y, w0.z, w0.w, w1.x, w1.y, w1.z, w1.w};
#pragma unroll
            for (int r = 0; r < 8; r++) {
                unsigned long long wb = bcast2(wr[r]);
#pragma unroll
                for (int c = 0; c < 4; c++) fma2(acc[r][c], wb, hh[c]);
            }
        }
    }

    // unpack accumulators
    float va[8][8];
#pragma unroll
    for (int r = 0; r < 8; r++) {
#pragma unroll
        for (int c = 0; c < 4; c++) {
            float2 t = unpack2(acc[r][c]);
            va[r][2 * c] = t.x;
            va[r][2 * c + 1] = t.y;
        }
    }

    // split tf32 hi/lo and store transposed: WhT[b][f][i]
#pragma unroll
    for (int ff = 0; ff < 8; ff++) {
        float hv[8], lv[8];
#pragma unroll
        for (int r = 0; r < 8; r++) {
            float x = va[r][ff];
            float hb = __uint_as_float(f2tf32(x));
            hv[r] = hb;
            lv[r] = __uint_as_float(f2tf32(x - hb));
        }
        size_t base = ((size_t)b * FF + fbase + ff) * NN + i0 + rbase;
        *(float4*)(g_WhTh + base)     = make_float4(hv[0], hv[1], hv[2], hv[3]);
        *(float4*)(g_WhTh + base + 4) = make_float4(hv[4], hv[5], hv[6], hv[7]);
        *(float4*)(g_WhTl + base)     = make_float4(lv[0], lv[1], lv[2], lv[3]);
        *(float4*)(g_WhTl + base + 4) = make_float4(lv[4], lv[5], lv[6], lv[7]);
    }
}

// =====================================================================
// Kernel B: si/sj from WhT (coalesced along i)
// =====================================================================
__global__ void __launch_bounds__(256) k_sisj(const float* __restrict__ a) {
    __shared__ float as[256];
    as[threadIdx.x] = a[threadIdx.x];
    __syncthreads();

    int idx = blockIdx.x * 256 + threadIdx.x;   // 0..BB*NN-1
    int b = idx >> 12;
    int i = idx & (NN - 1);

    const float* ph = g_WhTh + (size_t)b * FF * NN + i;
    const float* pl = g_WhTl + (size_t)b * FF * NN + i;
    float si = 0.f, sj = 0.f;
#pragma unroll 8
    for (int f = 0; f < FF; f++) {
        float w = ph[(size_t)f * NN] + pl[(size_t)f * NN];
        si += w * as[f];
        sj += w * as[f + FF];
    }
    g_si[idx] = si;
    g_sj[idx] = sj;
}

// =====================================================================
// Kernel C: fused masked-softmax + P @ Wh (tensor cores, 3xTF32) + ELU.
// CTA: 128 i-rows (8 warps x m16), full f=128; j streamed in tiles of 16.
// k-permutation: j_local = 4*q + khalf + 2*s  (q=lane%4, s=k-step)
//  -> A-fragment j's per thread are contiguous (int4 adj / float4 sj loads)
//  -> B-fragment rows per (s,m) are contiguous (single LDS.64)
// =====================================================================
__global__ void __launch_bounds__(256, 1) k_attn(const int* __restrict__ adj,
                                                 float* __restrict__ out) {
    const int b = blockIdx.y;
    const int i0 = blockIdx.x * 128;

    __shared__ float whS[2][128][18];   // [hi/lo][f][j(16)+pad2]  36KB

    const int tid = threadIdx.x;
    const int lane = tid & 31, w = tid >> 5;
    const int q = lane & 3, rl = lane >> 2;

    const int r0 = i0 + w * 16 + rl;
    const int r1 = r0 + 8;

    const float si0 = g_si[b * NN + r0];
    const float si1 = g_si[b * NN + r1];
    const int* adj0 = adj + ((size_t)b * NN + r0) * NN + 4 * q;
    const int* adj1 = adj + ((size_t)b * NN + r1) * NN + 4 * q;
    const float* sjB = g_sj + b * NN + 4 * q;

    float acc[16][4];
#pragma unroll
    for (int m = 0; m < 16; m++)
#pragma unroll
        for (int c = 0; c < 4; c++) acc[m][c] = 0.f;
    float z0 = 0.f, z1 = 0.f;

    // copy-role: 4 slots per thread covering 2 arrays x 128 f x 4 quads
    const float* gsrc[4];
    float* sdst[4];
#pragma unroll
    for (int k = 0; k < 4; k++) {
        int s = tid + 256 * k;
        int arr = s >> 9;
        int f = (s >> 2) & 127;
        int qq = s & 3;
        gsrc[k] = (arr ? g_WhTl : g_WhTh) + ((size_t)b * FF + f) * NN + qq * 4;
        sdst[k] = &whS[arr][f][qq * 4];
    }

    // prefetch tile 0
    float4 cbuf[4];
#pragma unroll
    for (int k = 0; k < 4; k++) cbuf[k] = *(const float4*)(gsrc[k]);
    int4 av0 = *(const int4*)(adj0);
    int4 av1 = *(const int4*)(adj1);
    float4 sjv = *(const float4*)(sjB);

    const float* bbase = &whS[0][rl][4 * q];   // per-thread B base (hi array)

    for (int j0 = 0; j0 < NN; j0 += TJ) {
        __syncthreads();   // previous tile fully consumed
#pragma unroll
        for (int k = 0; k < 4; k++) {
            float2* d = (float2*)sdst[k];
            d[0] = make_float2(cbuf[k].x, cbuf[k].y);
            d[1] = make_float2(cbuf[k].z, cbuf[k].w);
        }
        __syncthreads();

        // ---- generate P for this thread's 4 j's (rows r0, r1) ----
        float p0[4], p1[4];
        {
            const float sjr[4] = {sjv.x, sjv.y, sjv.z, sjv.w};
            const int ar0[4] = {av0.x, av0.y, av0.z, av0.w};
            const int ar1[4] = {av1.x, av1.y, av1.z, av1.w};
#pragma unroll
            for (int jj = 0; jj < 4; jj++) {
                float e0 = si0 + sjr[jj]; e0 = e0 > 0.f ? e0 : LALPHA * e0;
                float e1 = si1 + sjr[jj]; e1 = e1 > 0.f ? e1 : LALPHA * e1;
                p0[jj] = ar0[jj] > 0 ? __expf(e0) : 0.f;
                p1[jj] = ar1[jj] > 0 ? __expf(e1) : 0.f;
                z0 += p0[jj];
                z1 += p1[jj];
            }
        }

        // ---- prefetch next tile (hidden under the mma loop) ----
        int jn = j0 + TJ;
        if (jn < NN) {
#pragma unroll
            for (int k = 0; k < 4; k++) cbuf[k] = *(const float4*)(gsrc[k] + jn);
            av0 = *(const int4*)(adj0 + jn);
            av1 = *(const int4*)(adj1 + jn);
            sjv = *(const float4*)(sjB + jn);
        }

        // ---- A fragments (hi/lo split) + mma ----
#pragma unroll
        for (int s = 0; s < 2; s++) {
            unsigned ah[4], al[4];
            float pv[4] = {p0[2 * s], p1[2 * s], p0[2 * s + 1], p1[2 * s + 1]};
#pragma unroll
            for (int t = 0; t < 4; t++) {
                ah[t] = f2tf32(pv[t]);
                al[t] = f2tf32(pv[t] - __uint_as_float(ah[t]));
            }
#pragma unroll
            for (int m = 0; m < 16; m++) {
                const float* pB = bbase + m * (8 * 18) + 2 * s;
                uint2 bh = *(const uint2*)(pB);
                uint2 bl = *(const uint2*)(pB + 128 * 18);
                mma_tf32(acc[m], ah, bh.x, bh.y);
                mma_tf32(acc[m], ah, bl.x, bl.y);
                mma_tf32(acc[m], al, bh.x, bh.y);
            }
        }
    }

    // ---- Z reduction over q-lanes (same rl) ----
    z0 += __shfl_xor_sync(0xFFFFFFFFu, z0, 1);
    z0 += __shfl_xor_sync(0xFFFFFFFFu, z0, 2);
    z1 += __shfl_xor_sync(0xFFFFFFFFu, z1, 1);
    z1 += __shfl_xor_sync(0xFFFFFFFFu, z1, 2);
    const float iz0 = 1.0f / z0;
    const float iz1 = 1.0f / z1;

    // ---- epilogue: normalize + ELU + store ----
    float* out0 = out + ((size_t)b * NN + r0) * FF + 2 * q;
    float* out1 = out + ((size_t)b * NN + r1) * FF + 2 * q;
#pragma unroll
    for (int m = 0; m < 16; m++) {
        float v00 = acc[m][0] * iz0;
        float v01 = acc[m][1] * iz0;
        float v10 = acc[m][2] * iz1;
        float v11 = acc[m][3] * iz1;
        v00 = v00 > 0.f ? v00 : (__expf(v00) - 1.0f);
        v01 = v01 > 0.f ? v01 : (__expf(v01) - 1.0f);
        v10 = v10 > 0.f ? v10 : (__expf(v10) - 1.0f);
        v11 = v11 > 0.f ? v11 : (__expf(v11) - 1.0f);
        *(float2*)(out0 + m * 8) = make_float2(v00, v01);
        *(float2*)(out1 + m * 8) = make_float2(v10, v11);
    }
}

// =====================================================================
extern "C" void kernel_launch(void* const* d_in, const int* in_sizes, int n_in,
                              void* d_out, int out_size) {
    const float* h   = (const float*)d_in[0];
    const int*   adj = (const int*)d_in[1];
    const float* W   = (const float*)d_in[2];
    const float* a   = (const float*)d_in[3];
    float* out = (float*)d_out;

    k_wh<<<dim3(NN / 64, BB), 128>>>(h, W);
    k_sisj<<<BB * NN / 256, 256>>>(a);
    k_attn<<<dim3(NN / 128, BB), 256>>>(adj, out);
}

// round 5
// speedup vs baseline: 2.0815x; 1.6492x over previous
#include <cuda_runtime.h>
#include <cuda_bf16.h>
#include <cstdint>

#define BB 4
#define NN 4096
#define FF 128
#define NIT 256           // 4096 / 16 j-tiles

// ---------------- scratch (no allocations allowed) ----------------
__device__ uint4  g_WhTh[(size_t)BB * FF * NN / 8];   // WhT hi bf16 [b][f][j], 4MB
__device__ uint4  g_WhTl[(size_t)BB * FF * NN / 8];   // WhT lo bf16            4MB
__device__ float  g_si[BB * NN];
__device__ float2 g_uv[BB * NN];                      // {e^{sj}, e^{0.2 sj}}

// ---------------- helpers ----------------
__device__ __forceinline__ unsigned long long pack2(float lo, float hi) {
    unsigned long long r; asm("mov.b64 %0, {%1, %2};" : "=l"(r) : "f"(lo), "f"(hi)); return r;
}
__device__ __forceinline__ unsigned long long bcast2(float v) {
    unsigned long long r; asm("mov.b64 %0, {%1, %1};" : "=l"(r) : "f"(v)); return r;
}
__device__ __forceinline__ void fma2(unsigned long long& d, unsigned long long a, unsigned long long b) {
    asm("fma.rn.f32x2 %0, %1, %2, %0;" : "+l"(d) : "l"(a), "l"(b));
}
__device__ __forceinline__ float2 unpack2(unsigned long long v) {
    float2 f; asm("mov.b64 {%0, %1}, %2;" : "=f"(f.x), "=f"(f.y) : "l"(v)); return f;
}
// bf16 RNE (bits in upper half)
__device__ __forceinline__ uint32_t rnbf(float x) {
    uint32_t u = __float_as_uint(x);
    u += 0x7FFFu + ((u >> 16) & 1u);
    return u & 0xFFFF0000u;
}
// pack two floats -> bf16x2 (lo arg in low half)
__device__ __forceinline__ uint32_t pkbf2(float lo, float hi) {
    uint32_t r; asm("cvt.rn.bf16x2.f32 %0, %2, %1;" : "=r"(r) : "f"(lo), "f"(hi)); return r;
}
__device__ __forceinline__ void mma_bf16(float* c, uint32_t a0, uint32_t a1,
                                         uint32_t a2, uint32_t a3,
                                         uint32_t b0, uint32_t b1) {
    asm volatile(
        "mma.sync.aligned.m16n8k16.row.col.f32.bf16.bf16.f32 "
        "{%0,%1,%2,%3}, {%4,%5,%6,%7}, {%8,%9}, {%0,%1,%2,%3};"
        : "+f"(c[0]), "+f"(c[1]), "+f"(c[2]), "+f"(c[3])
        : "r"(a0), "r"(a1), "r"(a2), "r"(a3), "r"(b0), "r"(b1));
}

// =====================================================================
// Kernel A: Wh = h @ W ; epilogue splits bf16 hi/lo, stores WhT[b][f][j]
// =====================================================================
__global__ void __launch_bounds__(128) k_wh(const float* __restrict__ h,
                                            const float* __restrict__ W) {
    const int b = blockIdx.y;
    const int i0 = blockIdx.x * 64;

    __shared__ float hsT[32][68];
    __shared__ float Ws[32][128];

    const int tid = threadIdx.x;
    const int fgrp = tid & 15, rgrp = tid >> 4;
    const int rbase = rgrp * 8, fbase = fgrp * 8;

    unsigned long long acc[8][4];
#pragma unroll
    for (int r = 0; r < 8; r++)
#pragma unroll
        for (int c = 0; c < 4; c++) acc[r][c] = 0ULL;

    for (int k0 = 0; k0 < FF; k0 += 32) {
        __syncthreads();
        for (int idx = tid; idx < 64 * 8; idx += 128) {
            int r = idx >> 3, kq = idx & 7;
            float4 v = *(const float4*)(h + ((size_t)(b * NN + i0 + r)) * FF + k0 + kq * 4);
            hsT[kq * 4 + 0][r] = v.x;
            hsT[kq * 4 + 1][r] = v.y;
            hsT[kq * 4 + 2][r] = v.z;
            hsT[kq * 4 + 3][r] = v.w;
        }
        for (int idx = tid; idx < 32 * 32; idx += 128) {
            int kk = idx >> 5, fq = idx & 31;
            *(float4*)&Ws[kk][fq * 4] = *(const float4*)(W + (size_t)(k0 + kk) * FF + fq * 4);
        }
        __syncthreads();

#pragma unroll 4
        for (int kk = 0; kk < 32; kk++) {
            float4 w0 = *(float4*)&hsT[kk][rbase];
            float4 w1 = *(float4*)&hsT[kk][rbase + 4];
            float4 h0 = *(float4*)&Ws[kk][fbase];
            float4 h1 = *(float4*)&Ws[kk][fbase + 4];
            unsigned long long hh[4];
            hh[0] = pack2(h0.x, h0.y); hh[1] = pack2(h0.z, h0.w);
            hh[2] = pack2(h1.x, h1.y); hh[3] = pack2(h1.z, h1.w);
            float wr[8] = {w0.x, w0.y, w0.z, w0.w, w1.x, w1.y, w1.z, w1.w};
#pragma unroll
            for (int r = 0; r < 8; r++) {
                unsigned long long wb = bcast2(wr[r]);
#pragma unroll
                for (int c = 0; c < 4; c++) fma2(acc[r][c], wb, hh[c]);
            }
        }
    }

    float va[8][8];
#pragma unroll
    for (int r = 0; r < 8; r++) {
#pragma unroll
        for (int c = 0; c < 4; c++) {
            float2 t = unpack2(acc[r][c]);
            va[r][2 * c] = t.x;
            va[r][2 * c + 1] = t.y;
        }
    }

#pragma unroll
    for (int ffi = 0; ffi < 8; ffi++) {
        uint32_t hp[4], lp[4];
#pragma unroll
        for (int rp = 0; rp < 4; rp++) {
            float x0 = va[2 * rp][ffi], x1 = va[2 * rp + 1][ffi];
            uint32_t u0 = rnbf(x0), u1 = rnbf(x1);
            hp[rp] = (u1 & 0xFFFF0000u) | (u0 >> 16);
            lp[rp] = pkbf2(x0 - __uint_as_float(u0), x1 - __uint_as_float(u1));
        }
        size_t v4 = (((size_t)(b * FF) + fbase + ffi) * NN + i0 + rbase) >> 3;
        g_WhTh[v4] = make_uint4(hp[0], hp[1], hp[2], hp[3]);
        g_WhTl[v4] = make_uint4(lp[0], lp[1], lp[2], lp[3]);
    }
}

// =====================================================================
// Kernel B: si, (u=e^{sj}, v=e^{0.2 sj}) from bf16-pair WhT
// =====================================================================
__global__ void __launch_bounds__(256) k_sisj(const float* __restrict__ a) {
    __shared__ float as[256];
    as[threadIdx.x] = a[threadIdx.x];
    __syncthreads();

    int idx = blockIdx.x * 256 + threadIdx.x;
    int b = idx >> 12;
    int i = idx & (NN - 1);

    const __nv_bfloat16* ph = (const __nv_bfloat16*)g_WhTh + (size_t)b * FF * NN + i;
    const __nv_bfloat16* pl = (const __nv_bfloat16*)g_WhTl + (size_t)b * FF * NN + i;
    float si = 0.f, sj = 0.f;
#pragma unroll 16
    for (int f = 0; f < FF; f++) {
        float w = __bfloat162float(ph[(size_t)f * NN]) + __bfloat162float(pl[(size_t)f * NN]);
        si += w * as[f];
        sj += w * as[f + FF];
    }
    g_si[idx] = si;
    g_uv[idx] = make_float2(__expf(sj), __expf(0.2f * sj));
}

// =====================================================================
// Kernel C: fused masked-softmax + P @ Wh via mma.sync bf16 (3-term) + ELU
// CTA = 128 i-rows x 128 f, 8 warps (warp = 16 rows x 128 f), j tiles of 16.
// P generated in registers from rank-1 factors (no exp in hot loop).
// =====================================================================
__global__ void __launch_bounds__(256, 1) k_attn(const int* __restrict__ adj,
                                                 float* __restrict__ out) {
    __shared__ float2 uvS[NN];          // 32 KB: u,v for all j
    __shared__ uint4  stg4[1024];       // 16 KB: 2 stages x 2 arrays x 128f x 32B
    char* stg = (char*)stg4;

    const int tid = threadIdx.x;
    const int lane = tid & 31, w = tid >> 5;
    const int c = lane & 3, fq = lane >> 2;
    const int b = blockIdx.y;
    const int i0 = blockIdx.x * 128;

    // load u,v table
#pragma unroll
    for (int k = 0; k < 16; k++) {
        int idx = tid + 256 * k;
        uvS[idx] = g_uv[b * NN + idx];
    }

    // row constants
    const int r0 = i0 + w * 16 + fq;
    const int r1 = r0 + 8;
    const float si0 = g_si[b * NN + r0];
    const float si1 = g_si[b * NN + r1];
    const float c10 = __expf(si0), c20 = __expf(0.2f * si0), th0 = __expf(-si0);
    const float c11 = __expf(si1), c21 = __expf(0.2f * si1), th1 = __expf(-si1);

    const int2* a00 = (const int2*)(adj + ((size_t)(b * NN + r0)) * NN + 2 * c);
    const int2* a10 = (const int2*)(adj + ((size_t)(b * NN + r1)) * NN + 2 * c);
    // int2 index stride per j-tile: 16 j = 8 int2; +8 j = 4 int2

    // staging role: thread -> (arr, f)
    const int arr = tid >> 7;
    const int f = tid & 127;
    const int kf = f & 7;
    const uint4* src = (arr ? g_WhTl : g_WhTh) + (size_t)(b * FF + f) * (NN / 8);
    uint32_t* dst0 = (uint32_t*)(stg + arr * 4096 + f * 32);

    // consumer B addressing
    const int swz0 = ((c ^ fq) << 2);
    const int swz1 = (((c + 4) ^ fq) << 2);
    const char* bb = stg + fq * 32;
    const float2* uvp = uvS + 2 * c;

    float acc[16][4];
#pragma unroll
    for (int nt = 0; nt < 16; nt++)
#pragma unroll
        for (int k = 0; k < 4; k++) acc[nt][k] = 0.f;
    float z0 = 0.f, z1 = 0.f;

    // prologue prefetch
    uint4 cb0 = src[0], cb1 = src[1];
    int2 A00 = __ldcs(a00), A01 = __ldcs(a00 + 4);
    int2 A10 = __ldcs(a10), A11 = __ldcs(a10 + 4);

    auto compute = [&](int tc) {
        const int J = tc * 16;
        // u,v for this thread's 4 j's
        float4 uvA = *(const float4*)(uvp + J);       // u(2c),v(2c),u(2c+1),v(2c+1)
        float4 uvB = *(const float4*)(uvp + J + 8);   // +8 pair
        // P values
        float p00 = A00.x > 0 ? (uvA.x > th0 ? c10 * uvA.x : c20 * uvA.y) : 0.f;
        float p01 = A00.y > 0 ? (uvA.z > th0 ? c10 * uvA.z : c20 * uvA.w) : 0.f;
        float p08 = A01.x > 0 ? (uvB.x > th0 ? c10 * uvB.x : c20 * uvB.y) : 0.f;
        float p09 = A01.y > 0 ? (uvB.z > th0 ? c10 * uvB.z : c20 * uvB.w) : 0.f;
        float p10 = A10.x > 0 ? (uvA.x > th1 ? c11 * uvA.x : c21 * uvA.y) : 0.f;
        float p11 = A10.y > 0 ? (uvA.z > th1 ? c11 * uvA.z : c21 * uvA.w) : 0.f;
        float p18 = A11.x > 0 ? (uvB.x > th1 ? c11 * uvB.x : c21 * uvB.y) : 0.f;
        float p19 = A11.y > 0 ? (uvB.z > th1 ? c11 * uvB.z : c21 * uvB.w) : 0.f;
        z0 += (p00 + p01) + (p08 + p09);
        z1 += (p10 + p11) + (p18 + p19);

        // prefetch adj for next tile
        if (tc + 1 < NIT) {
            int o = (tc + 1) * 8;
            A00 = __ldcs(a00 + o); A01 = __ldcs(a00 + o + 4);
            A10 = __ldcs(a10 + o); A11 = __ldcs(a10 + o + 4);
        }

        // bf16 hi/lo split -> A fragments
        uint32_t h00 = rnbf(p00), h01 = rnbf(p01), h08 = rnbf(p08), h09 = rnbf(p09);
        uint32_t h10 = rnbf(p10), h11 = rnbf(p11), h18 = rnbf(p18), h19 = rnbf(p19);
        uint32_t ah0 = (h01 & 0xFFFF0000u) | (h00 >> 16);
        uint32_t ah1 = (h11 & 0xFFFF0000u) | (h10 >> 16);
        uint32_t ah2 = (h09 & 0xFFFF0000u) | (h08 >> 16);
        uint32_t ah3 = (h19 & 0xFFFF0000u) | (h18 >> 16);
        uint32_t al0 = pkbf2(p00 - __uint_as_float(h00), p01 - __uint_as_float(h01));
        uint32_t al1 = pkbf2(p10 - __uint_as_float(h10), p11 - __uint_as_float(h11));
        uint32_t al2 = pkbf2(p08 - __uint_as_float(h08), p09 - __uint_as_float(h09));
        uint32_t al3 = pkbf2(p18 - __uint_as_float(h18), p19 - __uint_as_float(h19));

        const char* sbb = bb + (tc & 1) * 8192;
#pragma unroll
        for (int nt = 0; nt < 16; nt++) {
            const char* pb = sbb + nt * 256;
            uint32_t bh0 = *(const uint32_t*)(pb + swz0);
            uint32_t bh1 = *(const uint32_t*)(pb + swz1);
            uint32_t bl0 = *(const uint32_t*)(pb + 4096 + swz0);
            uint32_t bl1 = *(const uint32_t*)(pb + 4096 + swz1);
            mma_bf16(acc[nt], ah0, ah1, ah2, ah3, bh0, bh1);
            mma_bf16(acc[nt], ah0, ah1, ah2, ah3, bl0, bl1);
            mma_bf16(acc[nt], al0, al1, al2, al3, bh0, bh1);
        }
    };

#pragma unroll 1
    for (int t = 0; t < NIT; t++) {
        __syncthreads();
        // STS tile t into stage t&1 (swizzled)
        uint32_t* d = dst0 + (t & 1) * 2048;   // 8192 bytes = 2048 words
        d[0 ^ kf] = cb0.x; d[1 ^ kf] = cb0.y; d[2 ^ kf] = cb0.z; d[3 ^ kf] = cb0.w;
        d[4 ^ kf] = cb1.x; d[5 ^ kf] = cb1.y; d[6 ^ kf] = cb1.z; d[7 ^ kf] = cb1.w;
        // prefetch next Wh tile
        if (t + 1 < NIT) { cb0 = src[2 * t + 2]; cb1 = src[2 * t + 3]; }
        if (t > 0) compute(t - 1);
    }
    __syncthreads();
    compute(NIT - 1);

    // Z reduction over the 4 lanes sharing a row
    z0 += __shfl_xor_sync(0xFFFFFFFFu, z0, 1);
    z0 += __shfl_xor_sync(0xFFFFFFFFu, z0, 2);
    z1 += __shfl_xor_sync(0xFFFFFFFFu, z1, 1);
    z1 += __shfl_xor_sync(0xFFFFFFFFu, z1, 2);
    const float iz0 = 1.0f / z0;
    const float iz1 = 1.0f / z1;

    float* o0 = out + ((size_t)(b * NN + r0)) * FF + 2 * c;
    float* o1 = out + ((size_t)(b * NN + r1)) * FF + 2 * c;
#pragma unroll
    for (int nt = 0; nt < 16; nt++) {
        float x0 = acc[nt][0] * iz0, x1 = acc[nt][1] * iz0;
        float y0 = acc[nt][2] * iz1, y1 = acc[nt][3] * iz1;
        x0 = x0 > 0.f ? x0 : (__expf(x0) - 1.0f);
        x1 = x1 > 0.f ? x1 : (__expf(x1) - 1.0f);
        y0 = y0 > 0.f ? y0 : (__expf(y0) - 1.0f);
        y1 = y1 > 0.f ? y1 : (__expf(y1) - 1.0f);
        *(float2*)(o0 + nt * 8) = make_float2(x0, x1);
        *(float2*)(o1 + nt * 8) = make_float2(y0, y1);
    }
}

// =====================================================================
extern "C" void kernel_launch(void* const* d_in, const int* in_sizes, int n_in,
                              void* d_out, int out_size) {
    const float* h   = (const float*)d_in[0];
    const int*   adj = (const int*)d_in[1];
    const float* W   = (const float*)d_in[2];
    const float* a   = (const float*)d_in[3];
    float* out = (float*)d_out;

    k_wh<<<dim3(NN / 64, BB), 128>>>(h, W);
    k_sisj<<<BB * NN / 256, 256>>>(a);
    k_attn<<<dim3(NN / 128, BB), 256>>>(adj, out);
}